// round 2
// baseline (speedup 1.0000x reference)
#include <cuda_runtime.h>
#include <math.h>

#define B     16
#define C     48
#define T     96
#define PATCH 12
#define FF    64
#define STEPS 7           // (T - PATCH) / PATCH
#define NF0   (C*T)       // 4608 features for BN0
#define NF1   (C*PATCH)   // 576 features for BN1/BN2
#define ALPHA 0.5f
#define EPS   1e-5f

// -------- scratch (no allocations allowed) --------
__device__ float g_xn[B*NF0];
__device__ float g_res[B*NF1];
__device__ float g_mu0[NF0], g_rs0[NF0];
__device__ float g_mu1[NF1], g_rs1[NF1];
__device__ float g_mu2[NF1], g_rs2[NF1];

__device__ __forceinline__ float gelu_exact(float x) {
    return 0.5f * x * (1.0f + erff(x * 0.70710678118654752f));
}

// ---------------- BN0 stats over batch (4608 features) ----------------
__global__ void k_stats0(const float* __restrict__ x) {
    int f = blockIdx.x * blockDim.x + threadIdx.x;
    if (f >= NF0) return;
    float v[B];
    float s = 0.f;
    #pragma unroll
    for (int b = 0; b < B; b++) { v[b] = x[b*NF0 + f]; s += v[b]; }
    float mu = s * (1.0f / B);
    float s2 = 0.f;
    #pragma unroll
    for (int b = 0; b < B; b++) { float d = v[b] - mu; s2 += d*d; }
    g_mu0[f] = mu;
    g_rs0[f] = rsqrtf(s2 * (1.0f / B) + EPS);
}

// ---------------- apply BN0 -> xn; write "first" into out ----------------
__global__ void k_apply0(const float* __restrict__ x, const float* __restrict__ g0,
                         const float* __restrict__ b0, float* __restrict__ out) {
    int idx = blockIdx.x * blockDim.x + threadIdx.x;
    if (idx >= B*NF0) return;
    int f = idx % NF0;
    float v = (x[idx] - g_mu0[f]) * g_rs0[f] * g0[f] + b0[f];
    g_xn[idx] = v;
    if ((f % T) < PATCH) out[idx] = v;   // first = xn[:,:,:PATCH], same (b,c,t) layout
}

// ---------------- BN1 stats over batch of prev (lives in out, segment s) ----------------
__global__ void k_stats1(const float* __restrict__ out, int s) {
    int f = threadIdx.x;                  // 576 threads, 1 block
    if (f >= NF1) return;
    int c = f / PATCH, p = f % PATCH;
    float v[B]; float sum = 0.f;
    #pragma unroll
    for (int b = 0; b < B; b++) {
        v[b] = out[(b*C + c)*T + s*PATCH + p];
        sum += v[b];
    }
    float mu = sum * (1.0f / B), s2 = 0.f;
    #pragma unroll
    for (int b = 0; b < B; b++) { float d = v[b] - mu; s2 += d*d; }
    g_mu1[f] = mu;
    g_rs1[f] = rsqrtf(s2 * (1.0f / B) + EPS);
}

// ---------------- BN2 stats over batch of res ----------------
__global__ void k_stats2() {
    int f = threadIdx.x;                  // 576 threads, 1 block
    if (f >= NF1) return;
    float v[B]; float sum = 0.f;
    #pragma unroll
    for (int b = 0; b < B; b++) { v[b] = g_res[b*NF1 + f]; sum += v[b]; }
    float mu = sum * (1.0f / B), s2 = 0.f;
    #pragma unroll
    for (int b = 0; b < B; b++) { float d = v[b] - mu; s2 += d*d; }
    g_mu2[f] = mu;
    g_rs2[f] = rsqrtf(s2 * (1.0f / B) + EPS);
}

// ---------------- BN1 apply + 12x12 agg matmul + gelu + residual -> res ----------------
__global__ void k_agg(const float* __restrict__ out,
                      const float* __restrict__ g1, const float* __restrict__ b1,
                      const float* __restrict__ Wagg, const float* __restrict__ bagg,
                      int s) {
    int r = blockIdx.x * blockDim.x + threadIdx.x;
    if (r >= B*C) return;
    int b = r / C, c = r % C;
    float inpn[PATCH];
    #pragma unroll
    for (int p = 0; p < PATCH; p++) {
        int f = c*PATCH + p;
        float v = out[(b*C + c)*T + s*PATCH + p];
        inpn[p] = (v - g_mu1[f]) * g_rs1[f] * g1[f] + b1[f];
    }
    #pragma unroll
    for (int q = 0; q < PATCH; q++) {
        float a = bagg[q];
        #pragma unroll
        for (int p = 0; p < PATCH; p++) a = fmaf(inpn[p], Wagg[q*PATCH + p], a);
        float g = gelu_exact(a);
        float xw = g_xn[(b*C + c)*T + PATCH + s*PATCH + q];
        g_res[b*NF1 + c*PATCH + q] = g + xw;
    }
}

// ---------------- main attention kernel ----------------
// grid = B*PATCH*SPLIT blocks; block (b,p,split) computes e rows i in [i0, i0+RPB)
#define SPLIT 3
#define RPB   16
__global__ void k_attn(const float* __restrict__ g2, const float* __restrict__ b2,
                       const float* __restrict__ W1, const float* __restrict__ bm1,
                       const float* __restrict__ W2, const float* __restrict__ bm2,
                       const float* __restrict__ wmsg, const float* __restrict__ bmsg,
                       float* __restrict__ out, int s) {
    __shared__ float st[C];
    __shared__ float su[FF*RPB];
    __shared__ float sv[FF*C];
    __shared__ float sw2[FF];
    __shared__ float se[RPB*(C+1)];

    int blk = blockIdx.x;
    int bp = blk / SPLIT, sp = blk % SPLIT;
    int b = bp / PATCH, p = bp % PATCH;
    int i0 = sp * RPB;
    int tid = threadIdx.x;   // 256 threads

    // t[b,p,c] = BN2(res)[b,c,p]
    if (tid < C) {
        int f = tid*PATCH + p;
        float v = g_res[b*NF1 + f];
        st[tid] = (v - g_mu2[f]) * g_rs2[f] * g2[f] + b2[f];
    }
    if (tid < FF) sw2[tid] = W2[tid];
    __syncthreads();

    // u[f][il] = t_{i0+il} * W1[f,0] + bm1[f]   (first-layer i-part, bias folded)
    for (int idx = tid; idx < FF*RPB; idx += 256) {
        int f = idx / RPB, il = idx % RPB;
        su[idx] = fmaf(st[i0 + il], W1[2*f], bm1[f]);
    }
    // v[f][j] = t_j * W1[f,1]
    for (int idx = tid; idx < FF*C; idx += 256) {
        int f = idx / C, j = idx % C;
        sv[idx] = st[j] * W1[2*f + 1];
    }
    __syncthreads();

    // e[il][j] = bm2 + sum_f w2[f] * gelu(u + v)   (768 pairs, 3 per thread)
    float bm2v = bm2[0];
    #pragma unroll
    for (int k = 0; k < 3; k++) {
        int pr = tid + k*256;
        int il = pr / C, j = pr % C;
        float acc = bm2v;
        #pragma unroll
        for (int f = 0; f < FF; f++) {
            float xx = su[f*RPB + il] + sv[f*C + j];
            acc = fmaf(sw2[f], gelu_exact(xx), acc);
        }
        se[il*(C+1) + j] = acc;
    }
    __syncthreads();

    // per-row top-3 (lower index wins ties, matching jax.lax.top_k),
    // softmax over the 3 survivors (masked others underflow to exactly 0), message agg
    int w = tid >> 5, lane = tid & 31;
    float wm = wmsg[0], bmv = bmsg[0];
    #pragma unroll
    for (int rr = 0; rr < 2; rr++) {
        int il = w*2 + rr;
        float va = se[il*(C+1) + lane];
        int   ja = lane;
        int   jb = lane + 32;
        float vb = (jb < C) ? se[il*(C+1) + jb] : -3.4e38f;

        float topv[3]; int topj[3];
        #pragma unroll
        for (int k = 0; k < 3; k++) {
            bool ta = (va > vb) || (va == vb && ja < jb);
            float v = ta ? va : vb;
            int   j = ta ? ja : jb;
            #pragma unroll
            for (int off = 16; off; off >>= 1) {
                float ov = __shfl_xor_sync(0xffffffffu, v, off);
                int   oj = __shfl_xor_sync(0xffffffffu, j, off);
                if (ov > v || (ov == v && oj < j)) { v = ov; j = oj; }
            }
            topv[k] = v; topj[k] = j;
            if (j == ja) va = -3.4e38f;
            if (j == jb) vb = -3.4e38f;
        }
        if (lane == 0) {
            float m  = topv[0];
            float e0 = expf(topv[0] - m), e1 = expf(topv[1] - m), e2 = expf(topv[2] - m);
            float dn = e0 + e1 + e2;
            float m0 = fmaf(st[topj[0]], wm, bmv);
            float m1 = fmaf(st[topj[1]], wm, bmv);
            float m2 = fmaf(st[topj[2]], wm, bmv);
            float znew = (e0*m0 + e1*m1 + e2*m2) / dn;
            int i = i0 + il;
            float resv = g_res[b*NF1 + i*PATCH + p];
            out[(b*C + i)*T + (s+1)*PATCH + p] = fmaf(ALPHA, znew, resv);
        }
    }
}

extern "C" void kernel_launch(void* const* d_in, const int* in_sizes, int n_in,
                              void* d_out, int out_size) {
    const float* x    = (const float*)d_in[0];
    const float* g0   = (const float*)d_in[1];
    const float* b0   = (const float*)d_in[2];
    const float* g1   = (const float*)d_in[3];
    const float* b1   = (const float*)d_in[4];
    const float* g2   = (const float*)d_in[5];
    const float* b2   = (const float*)d_in[6];
    const float* Wagg = (const float*)d_in[7];
    const float* bagg = (const float*)d_in[8];
    const float* W1   = (const float*)d_in[9];
    const float* bm1  = (const float*)d_in[10];
    const float* W2   = (const float*)d_in[11];
    const float* bm2  = (const float*)d_in[12];
    const float* wmsg = (const float*)d_in[13];
    const float* bmsg = (const float*)d_in[14];
    float* out = (float*)d_out;

    k_stats0<<<(NF0 + 255)/256, 256>>>(x);
    k_apply0<<<(B*NF0 + 255)/256, 256>>>(x, g0, b0, out);
    for (int s = 0; s < STEPS; s++) {
        k_stats1<<<1, NF1>>>(out, s);
        k_agg<<<(B*C + 255)/256, 256>>>(out, g1, b1, Wagg, bagg, s);
        k_stats2<<<1, NF1>>>();
        k_attn<<<B*PATCH*SPLIT, 256>>>(g2, b2, W1, bm1, W2, bm2, wmsg, bmsg, out, s);
    }
}